// round 9
// baseline (speedup 1.0000x reference)
#include <cuda_runtime.h>
#include <cuda_bf16.h>

// Problem constants
#define T_TYPES 27
#define N_NODES 16384
#define B_BATCH 256
#define IN_DIM  300
#define HID     128
#define OUT_DIM 64
#define TILE_B  8
#define N_TILES (B_BATCH / TILE_B)     // 32
#define ROW_F4  75                     // 300 floats = 75 float4 = 150 f32x2

// Scratch
__device__ __align__(16) float g_pooled[T_TYPES * B_BATCH * IN_DIM];
__device__ int g_ctr[T_TYPES * N_TILES];       // zero-init, self-resetting
__device__ int g_bounds[T_TYPES * (B_BATCH + 1)];

typedef unsigned long long ull;

__device__ __forceinline__ ull fma2(ull a, ull b, ull c) {
    ull d;
    asm("fma.rn.f32x2 %0, %1, %2, %3;" : "=l"(d) : "l"(a), "l"(b), "l"(c));
    return d;
}
__device__ __forceinline__ ull add2(ull a, ull b) {
    ull d;
    asm("add.rn.f32x2 %0, %1, %2;" : "=l"(d) : "l"(a), "l"(b));
    return d;
}
__device__ __forceinline__ ull mul2(ull a, ull b) {
    ull d;
    asm("mul.rn.f32x2 %0, %1, %2;" : "=l"(d) : "l"(a), "l"(b));
    return d;
}
__device__ __forceinline__ ull pack2(float x) {
    ull d; asm("mov.b64 %0, {%1, %1};" : "=l"(d) : "f"(x)); return d;
}
__device__ __forceinline__ void unpack2(ull v, float& lo, float& hi) {
    asm("mov.b64 {%0, %1}, %2;" : "=f"(lo), "=f"(hi) : "l"(v));
}

__device__ __forceinline__ int lower_bound_i32(const int* s, int n, int v) {
    int lo = 0, hi = n;
    while (lo < hi) {
        int mid = (lo + hi) >> 1;
        if (s[mid] < v) lo = mid + 1; else hi = mid;
    }
    return lo;
}

// ---------------------------------------------------------------------------
// Kernel 0: precompute segment bounds. grid=27, block=256.
// ---------------------------------------------------------------------------
__global__ void bounds_kernel(const int* __restrict__ seg) {
    const int t = blockIdx.x;
    const int b = threadIdx.x;
    const int* s = seg + (size_t)t * N_NODES;
    g_bounds[t * (B_BATCH + 1) + b] = lower_bound_i32(s, N_NODES, b);
    if (b == 0) g_bounds[t * (B_BATCH + 1) + B_BATCH] = N_NODES;
}

// ---------------------------------------------------------------------------
// Fused kernel: grid=(B,T), 128 threads, 10 blocks/SM target.
// Phase 1: all 4 warps stream rows (row-parallel), f32x2 packed accumulation.
// Phase 2: last block of each (t, 8-row) tile runs the 2-layer MLP inline
//          (may spill under the reg budget — off the critical path).
// ---------------------------------------------------------------------------
__global__ __launch_bounds__(128, 10)
void fused_kernel(const float* __restrict__ feat,
                  const float* __restrict__ W1,
                  const float* __restrict__ b1,
                  const float* __restrict__ W2,
                  const float* __restrict__ b2,
                  float* __restrict__ out) {
    const int b = blockIdx.x;
    const int t = blockIdx.y;
    const int tid = threadIdx.x;
    const int lane = tid & 31;
    const int w = tid >> 5;

    __shared__ __align__(16) float s_buf[IN_DIM * TILE_B];  // 9600 B (red/spt/ht)
    __shared__ int s_win;

    // ---------------- Phase 1: segment mean pooling ----------------
    const int lo  = g_bounds[t * (B_BATCH + 1) + b];
    const int cnt = g_bounds[t * (B_BATCH + 1) + b + 1] - lo;

    const bool has2 = lane < (ROW_F4 - 64);   // lane < 11
    ull acc[6];
    #pragma unroll
    for (int i = 0; i < 6; ++i) acc[i] = 0ull;
    const ulonglong2 z2 = make_ulonglong2(0ull, 0ull);

    {
        const ulonglong2* base =
            (const ulonglong2*)(feat + ((size_t)t * N_NODES + lo) * IN_DIM);
        int r = w;
        #pragma unroll 1
        for (; r + 4 < cnt; r += 8) {
            const ulonglong2* p0 = base + (size_t)r * ROW_F4;
            const ulonglong2* p1 = p0 + 4 * ROW_F4;
            ulonglong2 v0 = __ldcs(p0 + lane);
            ulonglong2 v1 = __ldcs(p0 + 32 + lane);
            ulonglong2 v2 = has2 ? __ldcs(p0 + 64 + lane) : z2;
            ulonglong2 u0 = __ldcs(p1 + lane);
            ulonglong2 u1 = __ldcs(p1 + 32 + lane);
            ulonglong2 u2 = has2 ? __ldcs(p1 + 64 + lane) : z2;
            acc[0] = add2(acc[0], v0.x); acc[1] = add2(acc[1], v0.y);
            acc[2] = add2(acc[2], v1.x); acc[3] = add2(acc[3], v1.y);
            acc[4] = add2(acc[4], v2.x); acc[5] = add2(acc[5], v2.y);
            acc[0] = add2(acc[0], u0.x); acc[1] = add2(acc[1], u0.y);
            acc[2] = add2(acc[2], u1.x); acc[3] = add2(acc[3], u1.y);
            acc[4] = add2(acc[4], u2.x); acc[5] = add2(acc[5], u2.y);
        }
        if (r < cnt) {
            const ulonglong2* p0 = base + (size_t)r * ROW_F4;
            ulonglong2 v0 = __ldcs(p0 + lane);
            ulonglong2 v1 = __ldcs(p0 + 32 + lane);
            ulonglong2 v2 = has2 ? __ldcs(p0 + 64 + lane) : z2;
            acc[0] = add2(acc[0], v0.x); acc[1] = add2(acc[1], v0.y);
            acc[2] = add2(acc[2], v1.x); acc[3] = add2(acc[3], v1.y);
            acc[4] = add2(acc[4], v2.x); acc[5] = add2(acc[5], v2.y);
        }
    }

    // cross-warp reduction via smem: red[w][col] (4 x 75 x 16B = 4800 B)
    {
        ulonglong2* red = (ulonglong2*)s_buf;
        red[w * ROW_F4 + lane]      = make_ulonglong2(acc[0], acc[1]);
        red[w * ROW_F4 + 32 + lane] = make_ulonglong2(acc[2], acc[3]);
        if (has2) red[w * ROW_F4 + 64 + lane] = make_ulonglong2(acc[4], acc[5]);
    }
    __syncthreads();

    if (tid < ROW_F4) {
        const ulonglong2* red = (const ulonglong2*)s_buf;
        ulonglong2 s0 = red[tid];
        ulonglong2 s1 = red[ROW_F4 + tid];
        ulonglong2 s2 = red[2 * ROW_F4 + tid];
        ulonglong2 s3 = red[3 * ROW_F4 + tid];
        const ull inv2 = pack2(1.0f / (float)max(cnt, 1));
        ull mx = mul2(add2(add2(s0.x, s1.x), add2(s2.x, s3.x)), inv2);
        ull my = mul2(add2(add2(s0.y, s1.y), add2(s2.y, s3.y)), inv2);
        ulonglong2* po =
            (ulonglong2*)(g_pooled + ((size_t)t * B_BATCH + b) * IN_DIM);
        po[tid] = make_ulonglong2(mx, my);
    }

    // ---------------- arrival & winner election ----------------
    __threadfence();                     // order each thread's pooled stores
    __syncthreads();
    const int tile = t * N_TILES + (b >> 3);
    if (tid == 0) {
        int old = atomicAdd(&g_ctr[tile], 1);
        if (old == TILE_B - 1) {
            atomicSub(&g_ctr[tile], TILE_B);   // self-reset for graph replays
            s_win = 1;
        } else {
            s_win = 0;
        }
    }
    __syncthreads();
    if (!s_win) return;
    __threadfence();                     // acquire before reading peers' rows

    // ---------------- Phase 2: MLP for tile rows [b0, b0+8) ----------------
    const int b0 = (b >> 3) * TILE_B;

    // load pooled tile [8 x 300] transposed into s_buf[k*8 + r]
    {
        const float* src = g_pooled + ((size_t)t * B_BATCH + b0) * IN_DIM;
        for (int idx = tid; idx < TILE_B * IN_DIM; idx += 128) {
            int r = idx / IN_DIM;
            int k = idx - r * IN_DIM;
            s_buf[k * TILE_B + r] = __ldcg(&src[idx]);
        }
    }
    __syncthreads();

    // GEMM1: h[r][j] = relu(sum_k sp[r][k]*W1[k][j] + b1[j]); j = tid
    const int j = tid;
    ull hacc[4];
    {
        ull binit = pack2(b1[t * HID + j]);
        #pragma unroll
        for (int p = 0; p < 4; ++p) hacc[p] = binit;

        const float* w1p = W1 + (size_t)t * IN_DIM * HID + j;
        float wc[10], wn[10];
        #pragma unroll
        for (int i = 0; i < 10; ++i) wc[i] = w1p[i * HID];

        for (int kg = 0; kg < IN_DIM / 10; ++kg) {
            const int kb = kg * 10;
            if (kg + 1 < IN_DIM / 10) {
                const float* wp2 = w1p + (kb + 10) * HID;
                #pragma unroll
                for (int i = 0; i < 10; ++i) wn[i] = wp2[i * HID];
            }
            #pragma unroll
            for (int q = 0; q < 10; ++q) {
                ull wp = pack2(wc[q]);
                const ulonglong2* sp = (const ulonglong2*)&s_buf[(kb + q) * TILE_B];
                ulonglong2 u0 = sp[0];
                ulonglong2 u1 = sp[1];
                hacc[0] = fma2(wp, u0.x, hacc[0]);
                hacc[1] = fma2(wp, u0.y, hacc[1]);
                hacc[2] = fma2(wp, u1.x, hacc[2]);
                hacc[3] = fma2(wp, u1.y, hacc[3]);
            }
            #pragma unroll
            for (int i = 0; i < 10; ++i) wc[i] = wn[i];
        }
    }
    __syncthreads();   // done reading spt; reuse s_buf for ht

    // relu + transposed store ht[j*8 + r]
    #pragma unroll
    for (int p = 0; p < 4; ++p) {
        float lo2, hi2;
        unpack2(hacc[p], lo2, hi2);
        *(float2*)&s_buf[j * TILE_B + 2 * p] =
            make_float2(fmaxf(lo2, 0.f), fmaxf(hi2, 0.f));
    }
    __syncthreads();

    // GEMM2: out[r][o] = sum_j h[r][j]*W2[j][o] + b2[o]
    const int o  = tid & 63;
    const int rh = tid >> 6;              // rows rh*4 .. rh*4+3 (2 pairs)
    ull c0, c1;
    {
        ull binit = pack2(b2[t * OUT_DIM + o]);
        c0 = binit; c1 = binit;

        const float* w2p = W2 + (size_t)t * HID * OUT_DIM + o;
        float wc[16], wn[16];
        #pragma unroll
        for (int i = 0; i < 16; ++i) wc[i] = w2p[i * OUT_DIM];

        for (int jg = 0; jg < HID / 16; ++jg) {
            const int jb = jg * 16;
            if (jg + 1 < HID / 16) {
                const float* wp2 = w2p + (jb + 16) * OUT_DIM;
                #pragma unroll
                for (int i = 0; i < 16; ++i) wn[i] = wp2[i * OUT_DIM];
            }
            #pragma unroll
            for (int q = 0; q < 16; ++q) {
                ull wp = pack2(wc[q]);
                ulonglong2 u =
                    *(const ulonglong2*)&s_buf[(jb + q) * TILE_B + rh * 4];
                c0 = fma2(wp, u.x, c0);
                c1 = fma2(wp, u.y, c1);
            }
            #pragma unroll
            for (int i = 0; i < 16; ++i) wc[i] = wn[i];
        }
    }

    // out layout: [B, T, OUT]
    {
        float lo2, hi2;
        unpack2(c0, lo2, hi2);
        out[((size_t)(b0 + rh * 4 + 0) * T_TYPES + t) * OUT_DIM + o] = lo2;
        out[((size_t)(b0 + rh * 4 + 1) * T_TYPES + t) * OUT_DIM + o] = hi2;
        unpack2(c1, lo2, hi2);
        out[((size_t)(b0 + rh * 4 + 2) * T_TYPES + t) * OUT_DIM + o] = lo2;
        out[((size_t)(b0 + rh * 4 + 3) * T_TYPES + t) * OUT_DIM + o] = hi2;
    }
}

// ---------------------------------------------------------------------------
extern "C" void kernel_launch(void* const* d_in, const int* in_sizes, int n_in,
                              void* d_out, int out_size) {
    const float* feat = (const float*)d_in[0];
    const int*   seg  = (const int*)d_in[1];
    const float* W1   = (const float*)d_in[2];
    const float* b1   = (const float*)d_in[3];
    const float* W2   = (const float*)d_in[4];
    const float* b2   = (const float*)d_in[5];
    float* out = (float*)d_out;

    bounds_kernel<<<T_TYPES, B_BATCH>>>(seg);

    dim3 grid(B_BATCH, T_TYPES);
    fused_kernel<<<grid, 128>>>(feat, W1, b1, W2, b2, out);
}

// round 10
// speedup vs baseline: 1.0203x; 1.0203x over previous
#include <cuda_runtime.h>
#include <cuda_bf16.h>

// Problem constants
#define T_TYPES 27
#define N_NODES 16384
#define B_BATCH 256
#define IN_DIM  300
#define HID     128
#define OUT_DIM 64
#define TILE_B  8
#define N_TILES (B_BATCH / TILE_B)     // 32
#define ROW_F4  75                     // 300 floats = 75 float4

// Scratch
__device__ __align__(16) float g_pooled[T_TYPES * B_BATCH * IN_DIM];
__device__ int g_ctr[T_TYPES * N_TILES];       // zero-init, self-resetting
__device__ int g_bounds[T_TYPES * (B_BATCH + 1)];

typedef unsigned long long ull;

__device__ __forceinline__ ull fma2(ull a, ull b, ull c) {
    ull d;
    asm("fma.rn.f32x2 %0, %1, %2, %3;" : "=l"(d) : "l"(a), "l"(b), "l"(c));
    return d;
}
__device__ __forceinline__ ull add2(ull a, ull b) {
    ull d;
    asm("add.rn.f32x2 %0, %1, %2;" : "=l"(d) : "l"(a), "l"(b));
    return d;
}
__device__ __forceinline__ ull mul2(ull a, ull b) {
    ull d;
    asm("mul.rn.f32x2 %0, %1, %2;" : "=l"(d) : "l"(a), "l"(b));
    return d;
}
__device__ __forceinline__ ull pack2(float x) {
    ull d; asm("mov.b64 %0, {%1, %1};" : "=l"(d) : "f"(x)); return d;
}
__device__ __forceinline__ void unpack2(ull v, float& lo, float& hi) {
    asm("mov.b64 {%0, %1}, %2;" : "=f"(lo), "=f"(hi) : "l"(v));
}

__device__ __forceinline__ int lower_bound_i32(const int* s, int n, int v) {
    int lo = 0, hi = n;
    while (lo < hi) {
        int mid = (lo + hi) >> 1;
        if (s[mid] < v) lo = mid + 1; else hi = mid;
    }
    return lo;
}

// ---------------------------------------------------------------------------
// Kernel 0: precompute segment bounds. grid=27, block=256.
// ---------------------------------------------------------------------------
__global__ void bounds_kernel(const int* __restrict__ seg) {
    const int t = blockIdx.x;
    const int b = threadIdx.x;
    const int* s = seg + (size_t)t * N_NODES;
    g_bounds[t * (B_BATCH + 1) + b] = lower_bound_i32(s, N_NODES, b);
    if (b == 0) g_bounds[t * (B_BATCH + 1) + B_BATCH] = N_NODES;
}

// ---------------------------------------------------------------------------
// Fused kernel: grid=(B,T), 128 threads, 8 blocks/SM.
// Phase 1: all 4 warps stream rows; 3 rows (9 LDG.128) in flight per warp.
// Phase 2: last block of each (t, 8-row) tile runs the 2-layer MLP inline.
// ---------------------------------------------------------------------------
__global__ __launch_bounds__(128, 8)
void fused_kernel(const float* __restrict__ feat,
                  const float* __restrict__ W1,
                  const float* __restrict__ b1,
                  const float* __restrict__ W2,
                  const float* __restrict__ b2,
                  float* __restrict__ out) {
    const int b = blockIdx.x;
    const int t = blockIdx.y;
    const int tid = threadIdx.x;
    const int lane = tid & 31;
    const int w = tid >> 5;

    __shared__ __align__(16) float s_buf[IN_DIM * TILE_B];  // 9600 B (red/spt/ht)
    __shared__ int s_win;

    // ---------------- Phase 1: segment mean pooling ----------------
    const int lo  = g_bounds[t * (B_BATCH + 1) + b];
    const int cnt = g_bounds[t * (B_BATCH + 1) + b + 1] - lo;

    const bool has2 = lane < (ROW_F4 - 64);   // lane < 11
    ull acc[6];
    #pragma unroll
    for (int i = 0; i < 6; ++i) acc[i] = 0ull;
    const ulonglong2 z2 = make_ulonglong2(0ull, 0ull);

    {
        const ulonglong2* base =
            (const ulonglong2*)(feat + ((size_t)t * N_NODES + lo) * IN_DIM);
        int r = w;
        #pragma unroll 1
        for (; r + 8 < cnt; r += 12) {
            const ulonglong2* p0 = base + (size_t)r * ROW_F4;
            const ulonglong2* p1 = p0 + 4 * ROW_F4;
            const ulonglong2* p2 = p0 + 8 * ROW_F4;
            ulonglong2 v0 = __ldcs(p0 + lane);
            ulonglong2 v1 = __ldcs(p0 + 32 + lane);
            ulonglong2 v2 = has2 ? __ldcs(p0 + 64 + lane) : z2;
            ulonglong2 u0 = __ldcs(p1 + lane);
            ulonglong2 u1 = __ldcs(p1 + 32 + lane);
            ulonglong2 u2 = has2 ? __ldcs(p1 + 64 + lane) : z2;
            ulonglong2 q0 = __ldcs(p2 + lane);
            ulonglong2 q1 = __ldcs(p2 + 32 + lane);
            ulonglong2 q2 = has2 ? __ldcs(p2 + 64 + lane) : z2;
            acc[0] = add2(acc[0], v0.x); acc[1] = add2(acc[1], v0.y);
            acc[2] = add2(acc[2], v1.x); acc[3] = add2(acc[3], v1.y);
            acc[4] = add2(acc[4], v2.x); acc[5] = add2(acc[5], v2.y);
            acc[0] = add2(acc[0], u0.x); acc[1] = add2(acc[1], u0.y);
            acc[2] = add2(acc[2], u1.x); acc[3] = add2(acc[3], u1.y);
            acc[4] = add2(acc[4], u2.x); acc[5] = add2(acc[5], u2.y);
            acc[0] = add2(acc[0], q0.x); acc[1] = add2(acc[1], q0.y);
            acc[2] = add2(acc[2], q1.x); acc[3] = add2(acc[3], q1.y);
            acc[4] = add2(acc[4], q2.x); acc[5] = add2(acc[5], q2.y);
        }
        #pragma unroll 1
        for (; r < cnt; r += 4) {
            const ulonglong2* p0 = base + (size_t)r * ROW_F4;
            ulonglong2 v0 = __ldcs(p0 + lane);
            ulonglong2 v1 = __ldcs(p0 + 32 + lane);
            ulonglong2 v2 = has2 ? __ldcs(p0 + 64 + lane) : z2;
            acc[0] = add2(acc[0], v0.x); acc[1] = add2(acc[1], v0.y);
            acc[2] = add2(acc[2], v1.x); acc[3] = add2(acc[3], v1.y);
            acc[4] = add2(acc[4], v2.x); acc[5] = add2(acc[5], v2.y);
        }
    }

    // cross-warp reduction via smem: red[w][col] (4 x 75 x 16B = 4800 B)
    {
        ulonglong2* red = (ulonglong2*)s_buf;
        red[w * ROW_F4 + lane]      = make_ulonglong2(acc[0], acc[1]);
        red[w * ROW_F4 + 32 + lane] = make_ulonglong2(acc[2], acc[3]);
        if (has2) red[w * ROW_F4 + 64 + lane] = make_ulonglong2(acc[4], acc[5]);
    }
    __syncthreads();

    if (tid < ROW_F4) {
        const ulonglong2* red = (const ulonglong2*)s_buf;
        ulonglong2 s0 = red[tid];
        ulonglong2 s1 = red[ROW_F4 + tid];
        ulonglong2 s2 = red[2 * ROW_F4 + tid];
        ulonglong2 s3 = red[3 * ROW_F4 + tid];
        const ull inv2 = pack2(1.0f / (float)max(cnt, 1));
        ull mx = mul2(add2(add2(s0.x, s1.x), add2(s2.x, s3.x)), inv2);
        ull my = mul2(add2(add2(s0.y, s1.y), add2(s2.y, s3.y)), inv2);
        ulonglong2* po =
            (ulonglong2*)(g_pooled + ((size_t)t * B_BATCH + b) * IN_DIM);
        po[tid] = make_ulonglong2(mx, my);
    }

    // ---------------- arrival & winner election ----------------
    __threadfence();                     // order each thread's pooled stores
    __syncthreads();
    const int tile = t * N_TILES + (b >> 3);
    if (tid == 0) {
        int old = atomicAdd(&g_ctr[tile], 1);
        if (old == TILE_B - 1) {
            atomicSub(&g_ctr[tile], TILE_B);   // self-reset for graph replays
            s_win = 1;
        } else {
            s_win = 0;
        }
    }
    __syncthreads();
    if (!s_win) return;
    __threadfence();                     // acquire before reading peers' rows

    // ---------------- Phase 2: MLP for tile rows [b0, b0+8) ----------------
    const int b0 = (b >> 3) * TILE_B;

    // load pooled tile [8 x 300] transposed into s_buf[k*8 + r]
    {
        const float* src = g_pooled + ((size_t)t * B_BATCH + b0) * IN_DIM;
        for (int idx = tid; idx < TILE_B * IN_DIM; idx += 128) {
            int r = idx / IN_DIM;
            int k = idx - r * IN_DIM;
            s_buf[k * TILE_B + r] = __ldcg(&src[idx]);
        }
    }
    __syncthreads();

    // GEMM1: h[r][j] = relu(sum_k sp[r][k]*W1[k][j] + b1[j]); j = tid
    const int j = tid;
    ull hacc[4];
    {
        ull binit = pack2(b1[t * HID + j]);
        #pragma unroll
        for (int p = 0; p < 4; ++p) hacc[p] = binit;

        const float* w1p = W1 + (size_t)t * IN_DIM * HID + j;
        float wc[10], wn[10];
        #pragma unroll
        for (int i = 0; i < 10; ++i) wc[i] = w1p[i * HID];

        for (int kg = 0; kg < IN_DIM / 10; ++kg) {
            const int kb = kg * 10;
            if (kg + 1 < IN_DIM / 10) {
                const float* wp2 = w1p + (kb + 10) * HID;
                #pragma unroll
                for (int i = 0; i < 10; ++i) wn[i] = wp2[i * HID];
            }
            #pragma unroll
            for (int q = 0; q < 10; ++q) {
                ull wp = pack2(wc[q]);
                const ulonglong2* sp = (const ulonglong2*)&s_buf[(kb + q) * TILE_B];
                ulonglong2 u0 = sp[0];
                ulonglong2 u1 = sp[1];
                hacc[0] = fma2(wp, u0.x, hacc[0]);
                hacc[1] = fma2(wp, u0.y, hacc[1]);
                hacc[2] = fma2(wp, u1.x, hacc[2]);
                hacc[3] = fma2(wp, u1.y, hacc[3]);
            }
            #pragma unroll
            for (int i = 0; i < 10; ++i) wc[i] = wn[i];
        }
    }
    __syncthreads();   // done reading spt; reuse s_buf for ht

    // relu + transposed store ht[j*8 + r]
    #pragma unroll
    for (int p = 0; p < 4; ++p) {
        float lo2, hi2;
        unpack2(hacc[p], lo2, hi2);
        *(float2*)&s_buf[j * TILE_B + 2 * p] =
            make_float2(fmaxf(lo2, 0.f), fmaxf(hi2, 0.f));
    }
    __syncthreads();

    // GEMM2: out[r][o] = sum_j h[r][j]*W2[j][o] + b2[o]
    const int o  = tid & 63;
    const int rh = tid >> 6;              // rows rh*4 .. rh*4+3 (2 pairs)
    ull c0, c1;
    {
        ull binit = pack2(b2[t * OUT_DIM + o]);
        c0 = binit; c1 = binit;

        const float* w2p = W2 + (size_t)t * HID * OUT_DIM + o;
        float wc[16], wn[16];
        #pragma unroll
        for (int i = 0; i < 16; ++i) wc[i] = w2p[i * OUT_DIM];

        for (int jg = 0; jg < HID / 16; ++jg) {
            const int jb = jg * 16;
            if (jg + 1 < HID / 16) {
                const float* wp2 = w2p + (jb + 16) * OUT_DIM;
                #pragma unroll
                for (int i = 0; i < 16; ++i) wn[i] = wp2[i * OUT_DIM];
            }
            #pragma unroll
            for (int q = 0; q < 16; ++q) {
                ull wp = pack2(wc[q]);
                ulonglong2 u =
                    *(const ulonglong2*)&s_buf[(jb + q) * TILE_B + rh * 4];
                c0 = fma2(wp, u.x, c0);
                c1 = fma2(wp, u.y, c1);
            }
            #pragma unroll
            for (int i = 0; i < 16; ++i) wc[i] = wn[i];
        }
    }

    // out layout: [B, T, OUT]
    {
        float lo2, hi2;
        unpack2(c0, lo2, hi2);
        out[((size_t)(b0 + rh * 4 + 0) * T_TYPES + t) * OUT_DIM + o] = lo2;
        out[((size_t)(b0 + rh * 4 + 1) * T_TYPES + t) * OUT_DIM + o] = hi2;
        unpack2(c1, lo2, hi2);
        out[((size_t)(b0 + rh * 4 + 2) * T_TYPES + t) * OUT_DIM + o] = lo2;
        out[((size_t)(b0 + rh * 4 + 3) * T_TYPES + t) * OUT_DIM + o] = hi2;
    }
}

// ---------------------------------------------------------------------------
extern "C" void kernel_launch(void* const* d_in, const int* in_sizes, int n_in,
                              void* d_out, int out_size) {
    const float* feat = (const float*)d_in[0];
    const int*   seg  = (const int*)d_in[1];
    const float* W1   = (const float*)d_in[2];
    const float* b1   = (const float*)d_in[3];
    const float* W2   = (const float*)d_in[4];
    const float* b2   = (const float*)d_in[5];
    float* out = (float*)d_out;

    bounds_kernel<<<T_TYPES, B_BATCH>>>(seg);

    dim3 grid(B_BATCH, T_TYPES);
    fused_kernel<<<grid, 128>>>(feat, W1, b1, W2, b2, out);
}